// round 1
// baseline (speedup 1.0000x reference)
#include <cuda_runtime.h>
#include <cuda_bf16.h>

#define MARGIN 0.4f

// Device-global scratch (no allocations allowed in kernel_launch).
__device__ float g_pos_sim;
__device__ float g_acc;

// ---------------------------------------------------------------------------
// Kernel 1: one warp computes pos_sim = dot(anchor, positive) over D=128,
// and zeroes the accumulator for this replay.
// ---------------------------------------------------------------------------
__global__ void tl_init_kernel(const float* __restrict__ anchor,
                               const float* __restrict__ positive) {
    int lane = threadIdx.x;  // launched with 32 threads
    const float4* a4 = reinterpret_cast<const float4*>(anchor);
    const float4* p4 = reinterpret_cast<const float4*>(positive);
    float4 av = a4[lane];
    float4 pv = p4[lane];
    float s = av.x * pv.x + av.y * pv.y + av.z * pv.z + av.w * pv.w;
    #pragma unroll
    for (int o = 16; o > 0; o >>= 1)
        s += __shfl_down_sync(0xffffffffu, s, o);
    if (lane == 0) {
        g_pos_sim = s;
        g_acc = 0.0f;
    }
}

// ---------------------------------------------------------------------------
// Kernel 2: streaming matvec + relu + sum.
// Warp-per-row, 4 rows per iteration (MLP=4), fully coalesced float4 loads.
// ---------------------------------------------------------------------------
__global__ void __launch_bounds__(256)
tl_main_kernel(const float* __restrict__ anchor,
               const float* __restrict__ negatives,
               int N) {
    const int lane = threadIdx.x & 31;
    const int warp_in_block = threadIdx.x >> 5;
    const long long gwarp = (long long)(blockIdx.x * (blockDim.x >> 5)) + warp_in_block;
    const long long nwarps = (long long)gridDim.x * (blockDim.x >> 5);

    // Anchor slice held in registers (16 B per lane covers D=128 across warp).
    const float4 av = reinterpret_cast<const float4*>(anchor)[lane];
    const float base = g_pos_sim + MARGIN;

    const float4* neg4 = reinterpret_cast<const float4*>(negatives);

    float sum = 0.0f;  // meaningful only at lane 0

    const long long stride = nwarps * 4;
    for (long long r0 = gwarp * 4; r0 < N; r0 += stride) {
        // Clamp row indices so tail loads stay in-bounds; contributions gated below.
        long long r1 = r0 + 1 < N ? r0 + 1 : (long long)N - 1;
        long long r2 = r0 + 2 < N ? r0 + 2 : (long long)N - 1;
        long long r3 = r0 + 3 < N ? r0 + 3 : (long long)N - 1;

        float4 v0 = neg4[r0 * 32 + lane];
        float4 v1 = neg4[r1 * 32 + lane];
        float4 v2 = neg4[r2 * 32 + lane];
        float4 v3 = neg4[r3 * 32 + lane];

        float s0 = av.x * v0.x + av.y * v0.y + av.z * v0.z + av.w * v0.w;
        float s1 = av.x * v1.x + av.y * v1.y + av.z * v1.z + av.w * v1.w;
        float s2 = av.x * v2.x + av.y * v2.y + av.z * v2.z + av.w * v2.w;
        float s3 = av.x * v3.x + av.y * v3.y + av.z * v3.z + av.w * v3.w;

        #pragma unroll
        for (int o = 16; o > 0; o >>= 1) {
            s0 += __shfl_down_sync(0xffffffffu, s0, o);
            s1 += __shfl_down_sync(0xffffffffu, s1, o);
            s2 += __shfl_down_sync(0xffffffffu, s2, o);
            s3 += __shfl_down_sync(0xffffffffu, s3, o);
        }

        if (lane == 0) {
            sum += fmaxf(base - s0, 0.0f);
            if (r0 + 1 < N) sum += fmaxf(base - s1, 0.0f);
            if (r0 + 2 < N) sum += fmaxf(base - s2, 0.0f);
            if (r0 + 3 < N) sum += fmaxf(base - s3, 0.0f);
        }
    }

    // Block reduce: one partial per warp (lane 0), then one atomic per block.
    __shared__ float warp_sums[8];  // 256 threads = 8 warps
    if (lane == 0) warp_sums[warp_in_block] = sum;
    __syncthreads();
    if (threadIdx.x == 0) {
        float bsum = 0.0f;
        #pragma unroll
        for (int w = 0; w < 8; w++) bsum += warp_sums[w];
        atomicAdd(&g_acc, bsum);
    }
}

// ---------------------------------------------------------------------------
// Kernel 3: finalize mean.
// ---------------------------------------------------------------------------
__global__ void tl_final_kernel(float* __restrict__ out, int N) {
    out[0] = g_acc / (float)N;
}

extern "C" void kernel_launch(void* const* d_in, const int* in_sizes, int n_in,
                              void* d_out, int out_size) {
    const float* anchor    = (const float*)d_in[0];
    const float* positive  = (const float*)d_in[1];
    const float* negatives = (const float*)d_in[2];
    float* out = (float*)d_out;

    const int D = 128;
    const int N = in_sizes[2] / D;  // 500000

    tl_init_kernel<<<1, 32>>>(anchor, positive);

    // 148 SMs * 8 blocks of 256 threads = one full-residency wave.
    const int blocks = 148 * 8;
    tl_main_kernel<<<blocks, 256>>>(anchor, negatives, N);

    tl_final_kernel<<<1, 1>>>(out, N);
}

// round 2
// speedup vs baseline: 1.0846x; 1.0846x over previous
#include <cuda_runtime.h>
#include <cuda_bf16.h>

#define MARGIN 0.4f

// Device-global scratch (no allocations allowed anywhere).
__device__ float        g_acc     = 0.0f;
__device__ unsigned int g_counter = 0u;

// ---------------------------------------------------------------------------
// Single fused persistent kernel:
//  - every warp redundantly computes pos_sim = dot(anchor, positive)  (cheap,
//    512 B, L2-resident, fully overlapped with the stream below)
//  - warp-per-row streaming matvec, 8 rows/iter (MLP=8), coalesced float4
//  - block reduce -> one atomicAdd per block -> last block writes mean and
//    resets the accumulator (graph-replay deterministic)
// ---------------------------------------------------------------------------
__global__ void __launch_bounds__(256)
tl_fused_kernel(const float* __restrict__ anchor,
                const float* __restrict__ positive,
                const float* __restrict__ negatives,
                float* __restrict__ out,
                int N) {
    const int lane = threadIdx.x & 31;
    const int warp_in_block = threadIdx.x >> 5;
    const long long gwarp  = (long long)(blockIdx.x * (blockDim.x >> 5)) + warp_in_block;
    const long long nwarps = (long long)gridDim.x * (blockDim.x >> 5);

    // Anchor slice in registers (lane*16B covers D=128 across the warp).
    const float4 av = reinterpret_cast<const float4*>(anchor)[lane];

    // pos_sim computed redundantly per warp (no cross-warp dependency).
    {
        // nothing: fold into base below
    }
    float base;
    {
        const float4 pv = reinterpret_cast<const float4*>(positive)[lane];
        float s = av.x * pv.x + av.y * pv.y + av.z * pv.z + av.w * pv.w;
        #pragma unroll
        for (int o = 16; o > 0; o >>= 1)
            s += __shfl_xor_sync(0xffffffffu, s, o);
        base = s + MARGIN;   // identical in all lanes after xor-reduce
    }

    const float4* __restrict__ neg4 = reinterpret_cast<const float4*>(negatives);

    float sum = 0.0f;  // meaningful only at lane 0

    const long long stride = nwarps * 8;
    for (long long r0 = gwarp * 8; r0 < N; r0 += stride) {
        // Clamp tail indices; contributions gated below. Duplicate loads OK.
        long long r[8];
        #pragma unroll
        for (int i = 0; i < 8; i++) {
            long long ri = r0 + i;
            r[i] = ri < N ? ri : (long long)N - 1;
        }

        // Front-batched loads: 8 independent LDG.128 in flight per lane.
        float4 v0 = neg4[r[0] * 32 + lane];
        float4 v1 = neg4[r[1] * 32 + lane];
        float4 v2 = neg4[r[2] * 32 + lane];
        float4 v3 = neg4[r[3] * 32 + lane];
        float4 v4 = neg4[r[4] * 32 + lane];
        float4 v5 = neg4[r[5] * 32 + lane];
        float4 v6 = neg4[r[6] * 32 + lane];
        float4 v7 = neg4[r[7] * 32 + lane];

        float s0 = av.x * v0.x + av.y * v0.y + av.z * v0.z + av.w * v0.w;
        float s1 = av.x * v1.x + av.y * v1.y + av.z * v1.z + av.w * v1.w;
        float s2 = av.x * v2.x + av.y * v2.y + av.z * v2.z + av.w * v2.w;
        float s3 = av.x * v3.x + av.y * v3.y + av.z * v3.z + av.w * v3.w;
        float s4 = av.x * v4.x + av.y * v4.y + av.z * v4.z + av.w * v4.w;
        float s5 = av.x * v5.x + av.y * v5.y + av.z * v5.z + av.w * v5.w;
        float s6 = av.x * v6.x + av.y * v6.y + av.z * v6.z + av.w * v6.w;
        float s7 = av.x * v7.x + av.y * v7.y + av.z * v7.z + av.w * v7.w;

        #pragma unroll
        for (int o = 16; o > 0; o >>= 1) {
            s0 += __shfl_down_sync(0xffffffffu, s0, o);
            s1 += __shfl_down_sync(0xffffffffu, s1, o);
            s2 += __shfl_down_sync(0xffffffffu, s2, o);
            s3 += __shfl_down_sync(0xffffffffu, s3, o);
            s4 += __shfl_down_sync(0xffffffffu, s4, o);
            s5 += __shfl_down_sync(0xffffffffu, s5, o);
            s6 += __shfl_down_sync(0xffffffffu, s6, o);
            s7 += __shfl_down_sync(0xffffffffu, s7, o);
        }

        if (lane == 0) {
            float t = 0.0f;
            t += fmaxf(base - s0, 0.0f);
            if (r0 + 1 < N) t += fmaxf(base - s1, 0.0f);
            if (r0 + 2 < N) t += fmaxf(base - s2, 0.0f);
            if (r0 + 3 < N) t += fmaxf(base - s3, 0.0f);
            if (r0 + 4 < N) t += fmaxf(base - s4, 0.0f);
            if (r0 + 5 < N) t += fmaxf(base - s5, 0.0f);
            if (r0 + 6 < N) t += fmaxf(base - s6, 0.0f);
            if (r0 + 7 < N) t += fmaxf(base - s7, 0.0f);
            sum += t;
        }
    }

    // Block reduce: one partial per warp (lane 0), then one atomic per block.
    __shared__ float warp_sums[8];  // 256 threads = 8 warps
    if (lane == 0) warp_sums[warp_in_block] = sum;
    __syncthreads();

    if (threadIdx.x == 0) {
        float bsum = 0.0f;
        #pragma unroll
        for (int w = 0; w < 8; w++) bsum += warp_sums[w];
        atomicAdd(&g_acc, bsum);
        __threadfence();
        // atomicInc wraps to 0 at gridDim.x-1 -> counter self-resets each replay.
        unsigned int ticket = atomicInc(&g_counter, gridDim.x - 1);
        if (ticket == gridDim.x - 1) {
            // Last block: all atomicAdds (incl. ours) are globally visible.
            float total = *((volatile float*)&g_acc);
            out[0] = total / (float)N;
            *((volatile float*)&g_acc) = 0.0f;   // reset for next graph replay
        }
    }
}

extern "C" void kernel_launch(void* const* d_in, const int* in_sizes, int n_in,
                              void* d_out, int out_size) {
    const float* anchor    = (const float*)d_in[0];
    const float* positive  = (const float*)d_in[1];
    const float* negatives = (const float*)d_in[2];
    float* out = (float*)d_out;

    const int D = 128;
    const int N = in_sizes[2] / D;  // 500000

    // 148 SMs * 4 blocks of 256 threads; MLP=8 per warp carries latency hiding.
    const int blocks = 148 * 4;
    tl_fused_kernel<<<blocks, 256>>>(anchor, positive, negatives, out, N);
}